// round 10
// baseline (speedup 1.0000x reference)
#include <cuda_runtime.h>
#include <cuda_bf16.h>
#include <cstdint>
#include <cstddef>

#define Bsz 128
#define Tt  256
#define Dd  256
#define Hh  1024
#define Cc  1000

// ---------------- static device scratch (no allocations) ----------------
// xproj layout: [t][j(32)][n(128)][b(128)], n = gate*32 + hcol_local, bias added.
__device__ float g_xproj[(size_t)Tt * 32 * 128 * 128];   // 512 MB
// h ping-pong, batch-DUPLICATED layout: g_h[p][k*256 + 2*b + {0,1}]
__device__ float g_h[2][(size_t)Hh * 256];
__device__ float g_c[(size_t)Hh * Bsz];                  // cell state [k][b]

// ---------------- packed fp32x2 helpers ----------------
__device__ __forceinline__ unsigned long long pack2(float lo, float hi) {
    unsigned long long r;
    asm("mov.b64 %0, {%1, %2};" : "=l"(r) : "f"(lo), "f"(hi));
    return r;
}
__device__ __forceinline__ void fma2(unsigned long long &acc,
                                     unsigned long long a, unsigned long long b) {
    asm("fma.rn.f32x2 %0, %1, %2, %0;" : "+l"(acc) : "l"(a), "l"(b));
}
__device__ __forceinline__ float sigm(float x) {
    return __fdividef(1.f, 1.f + __expf(-x));
}
__device__ __forceinline__ float tanhx(float x) {
    return 1.f - __fdividef(2.f, __expf(2.f * x) + 1.f);
}
__device__ __forceinline__ void cpa16(uint32_t dst, const void* src) {
    asm volatile("cp.async.cg.shared.global [%0], [%1], 16;" :: "r"(dst), "l"(src));
}
__device__ __forceinline__ void cpa_commit() {
    asm volatile("cp.async.commit_group;");
}
__device__ __forceinline__ void cpa_wait0() {
    asm volatile("cp.async.wait_group 0;");
}

// ---------------- init: zero h0 (dup layout) and c0 ----------------
__global__ void k_init() {
    int i = blockIdx.x * blockDim.x + threadIdx.x;
    if (i < Hh * 256) g_h[0][i] = 0.f;
    if (i < Hh * Bsz) g_c[i] = 0.f;
}

// ---------------- phase 1: input projections ----------------
__global__ __launch_bounds__(256, 2) void k_input_proj(
    const float* __restrict__ x,
    const float* __restrict__ Wg, const float* __restrict__ Wi,
    const float* __restrict__ Wf, const float* __restrict__ Wo,
    const float* __restrict__ bg, const float* __restrict__ bi,
    const float* __restrict__ bf, const float* __restrict__ bo)
{
    __shared__ float Ws[32][128];
    __shared__ float Xs[32][132];
    int j = blockIdx.x, t = blockIdx.y;
    int tid = threadIdx.x;
    int tn = tid & 15, tb = tid >> 4;
    int n0 = tn * 8, b0 = tb * 8;
    int jb = j * 32;

    int c4w = tid & 31;                 // 32 float4 per W row
    int gatew = c4w >> 3;
    const float* Wsel = (gatew < 2) ? (gatew == 0 ? Wg : Wi) : (gatew == 2 ? Wf : Wo);
    const float* wsrc0 = Wsel + jb + (c4w & 7) * 4;

    unsigned long long acc[32];
#pragma unroll
    for (int q = 0; q < 32; q++) acc[q] = 0ull;

    for (int kc = 0; kc < Dd / 32; kc++) {
        int k0 = kc * 32;
#pragma unroll
        for (int p = 0; p < 4; p++) {
            int row = p * 8 + (tid >> 5);
            *(float4*)&Ws[row][c4w * 4] = *(const float4*)(wsrc0 + (size_t)(k0 + row) * Hh);
        }
#pragma unroll
        for (int p = 0; p < 4; p++) {
            int fi = p * 256 + tid;
            int b = fi >> 3, d4 = fi & 7;
            float4 v = *(const float4*)&x[((size_t)b * Tt + t) * Dd + k0 + d4 * 4];
            Xs[d4 * 4 + 0][b] = v.x; Xs[d4 * 4 + 1][b] = v.y;
            Xs[d4 * 4 + 2][b] = v.z; Xs[d4 * 4 + 3][b] = v.w;
        }
        __syncthreads();
#pragma unroll 4
        for (int kr = 0; kr < 32; kr++) {
            float4 wA = *(const float4*)&Ws[kr][n0];
            float4 wB = *(const float4*)&Ws[kr][n0 + 4];
            float4 xA = *(const float4*)&Xs[kr][b0];
            float4 xB = *(const float4*)&Xs[kr][b0 + 4];
            unsigned long long w0 = pack2(wA.x, wA.y), w1 = pack2(wA.z, wA.w);
            unsigned long long w2 = pack2(wB.x, wB.y), w3 = pack2(wB.z, wB.w);
            float xv[8] = {xA.x, xA.y, xA.z, xA.w, xB.x, xB.y, xB.z, xB.w};
#pragma unroll
            for (int b = 0; b < 8; b++) {
                unsigned long long xb = pack2(xv[b], xv[b]);
                fma2(acc[0 * 8 + b], w0, xb);
                fma2(acc[1 * 8 + b], w1, xb);
                fma2(acc[2 * 8 + b], w2, xb);
                fma2(acc[3 * 8 + b], w3, xb);
            }
        }
        __syncthreads();
    }
    float* outp = g_xproj + (((size_t)t * 32 + j) * 128) * 128;
    int gate = n0 >> 5;
    const float* bsel = (gate < 2) ? (gate == 0 ? bg : bi) : (gate == 2 ? bf : bo);
#pragma unroll
    for (int np = 0; np < 4; np++) {
        int n = n0 + 2 * np;
        float bia0 = bsel[jb + (n & 31)];
        float bia1 = bsel[jb + ((n + 1) & 31)];
#pragma unroll
        for (int b = 0; b < 8; b++) {
            float2 v = *(float2*)&acc[np * 8 + b];
            outp[(size_t)n * 128 + b0 + b]       = v.x + bia0;
            outp[(size_t)(n + 1) * 128 + b0 + b] = v.y + bia1;
        }
    }
}

// ---------------- phase 2: one LSTM step, v3 (software-pipelined inner loop) ----------------
// grid (4 bb, 32 j), 256 threads = 2 warpgroups splitting K.
// CTA tile: 128 n (32 hcols x 4 gates) x 32 batch. Thread tile 8n x 4b.
// Dynamic smem: Wsd[2wg][2buf][32][128] | Hsd[2wg][2buf][32][64] | Ps[2][128][33]
#define STEP_SMEM_FLOATS (16384 + 8192 + 2 * 128 * 33)
__global__ __launch_bounds__(256, 1) void k_step(int s,
    const float* __restrict__ Wg, const float* __restrict__ Wi,
    const float* __restrict__ Wf, const float* __restrict__ Wo)
{
    extern __shared__ float sm[];
    float* Wsd = sm;                 // 16384 floats
    float* Hsd = sm + 16384;         // 8192 floats
    float* Ps  = sm + 24576;         // 8448 floats

    int bb = blockIdx.x, j = blockIdx.y;
    int tid = threadIdx.x;
    int wg = tid >> 7;
    int wt = tid & 127;
    int tn = wt & 15, tb = wt >> 4;
    int n0 = tn * 8, b0 = tb * 4;
    int jb = j * 32, bbase = bb * 32;
    const float* hin = g_h[s & 1];
    float* hout = g_h[(s + 1) & 1];

    // per-thread cp.async source bases
    int c4w = wt & 31;              // W: 32 float4/row
    int gatew = c4w >> 3;
    const float* Wsel = (gatew < 2) ? (gatew == 0 ? Wg : Wi) : (gatew == 2 ? Wf : Wo);
    const float* wsrc0 = Wsel + jb + (c4w & 7) * 4;
    int wrow0 = wt >> 5;            // + p*4, p<8
    int c4h = wt & 15;              // H: 16 float4/row (64 dup floats)
    const float* hsrc0 = hin + (size_t)bbase * 2 + c4h * 4;
    int hrow0 = wt >> 4;            // + p*8, p<4

    uint32_t wdstb = (uint32_t)__cvta_generic_to_shared(Wsd + (wg * 2) * 32 * 128);
    uint32_t hdstb = (uint32_t)__cvta_generic_to_shared(Hsd + (wg * 2) * 32 * 64);

    // init acc: wg0 from xproj (bias included), wg1 zero
    unsigned long long acc[16];
    if (wg == 0) {
        const float* xp = g_xproj + (((size_t)s * 32 + j) * 128) * 128 + bbase;
#pragma unroll
        for (int np = 0; np < 4; np++) {
            float4 r0 = *(const float4*)&xp[(size_t)(n0 + 2 * np) * 128 + b0];
            float4 r1 = *(const float4*)&xp[(size_t)(n0 + 2 * np + 1) * 128 + b0];
            acc[np * 4 + 0] = pack2(r0.x, r1.x);
            acc[np * 4 + 1] = pack2(r0.y, r1.y);
            acc[np * 4 + 2] = pack2(r0.z, r1.z);
            acc[np * 4 + 3] = pack2(r0.w, r1.w);
        }
    } else {
#pragma unroll
        for (int q = 0; q < 16; q++) acc[q] = 0ull;
    }

    // prefetch kc=0 into buf 0
    {
        int k0 = wg * 512;
#pragma unroll
        for (int p = 0; p < 8; p++) {
            int row = wrow0 + p * 4;
            cpa16(wdstb + (uint32_t)(row * 128 + c4w * 4) * 4,
                  wsrc0 + (size_t)(k0 + row) * Hh);
        }
#pragma unroll
        for (int p = 0; p < 4; p++) {
            int row = hrow0 + p * 8;
            cpa16(hdstb + (uint32_t)(row * 64 + c4h * 4) * 4,
                  hsrc0 + (size_t)(k0 + row) * 256);
        }
        cpa_commit();
    }

    int buf = 0;
    for (int kcl = 0; kcl < 16; kcl++) {
        cpa_wait0();
        __syncthreads();
        // prefetch next tile into the other buffer; its previous readers
        // retired at the bottom sync of iteration kcl-1.
        if (kcl < 15) {
            int k0 = wg * 512 + (kcl + 1) * 32;
            uint32_t wd = wdstb + (uint32_t)((buf ^ 1) * 32 * 128) * 4;
            uint32_t hd = hdstb + (uint32_t)((buf ^ 1) * 32 * 64) * 4;
#pragma unroll
            for (int p = 0; p < 8; p++) {
                int row = wrow0 + p * 4;
                cpa16(wd + (uint32_t)(row * 128 + c4w * 4) * 4,
                      wsrc0 + (size_t)(k0 + row) * Hh);
            }
#pragma unroll
            for (int p = 0; p < 4; p++) {
                int row = hrow0 + p * 8;
                cpa16(hd + (uint32_t)(row * 64 + c4h * 4) * 4,
                      hsrc0 + (size_t)(k0 + row) * 256);
            }
            cpa_commit();
        }
        const float* Wb = Wsd + (wg * 2 + buf) * 32 * 128;
        const float* Hb = Hsd + (wg * 2 + buf) * 32 * 64;

        // ---- software-pipelined FFMA2 core: load kr+1 before FMAing kr ----
        ulonglong2 cwA = *(const ulonglong2*)(Wb + n0);
        ulonglong2 cwB = *(const ulonglong2*)(Wb + n0 + 4);
        ulonglong2 chA = *(const ulonglong2*)(Hb + b0 * 2);
        ulonglong2 chB = *(const ulonglong2*)(Hb + b0 * 2 + 4);
#pragma unroll
        for (int kr = 0; kr < 32; kr++) {
            ulonglong2 nwA, nwB, nhA, nhB;
            if (kr < 31) {
                nwA = *(const ulonglong2*)(Wb + (kr + 1) * 128 + n0);
                nwB = *(const ulonglong2*)(Wb + (kr + 1) * 128 + n0 + 4);
                nhA = *(const ulonglong2*)(Hb + (kr + 1) * 64 + b0 * 2);
                nhB = *(const ulonglong2*)(Hb + (kr + 1) * 64 + b0 * 2 + 4);
            }
            fma2(acc[0],  cwA.x, chA.x); fma2(acc[1],  cwA.x, chA.y);
            fma2(acc[2],  cwA.x, chB.x); fma2(acc[3],  cwA.x, chB.y);
            fma2(acc[4],  cwA.y, chA.x); fma2(acc[5],  cwA.y, chA.y);
            fma2(acc[6],  cwA.y, chB.x); fma2(acc[7],  cwA.y, chB.y);
            fma2(acc[8],  cwB.x, chA.x); fma2(acc[9],  cwB.x, chA.y);
            fma2(acc[10], cwB.x, chB.x); fma2(acc[11], cwB.x, chB.y);
            fma2(acc[12], cwB.y, chA.x); fma2(acc[13], cwB.y, chA.y);
            fma2(acc[14], cwB.y, chB.x); fma2(acc[15], cwB.y, chB.y);
            if (kr < 31) { cwA = nwA; cwB = nwB; chA = nhA; chB = nhB; }
        }
        buf ^= 1;
        if (kcl < 15) __syncthreads();
    }

    // store partials, reduce across warpgroups, fuse gates
    float* myPs = Ps + wg * 128 * 33;
#pragma unroll
    for (int np = 0; np < 4; np++)
#pragma unroll
        for (int q = 0; q < 4; q++) {
            float2 v = *(float2*)&acc[np * 4 + q];
            myPs[(n0 + 2 * np) * 33 + b0 + q]     = v.x;
            myPs[(n0 + 2 * np + 1) * 33 + b0 + q] = v.y;
        }
    __syncthreads();

    int hcl = tid >> 3, bq = (tid & 7) * 4;
#pragma unroll
    for (int i2 = 0; i2 < 4; i2++) {
        int b = bq + i2;
        float pg = Ps[hcl * 33 + b]          + Ps[128 * 33 + hcl * 33 + b];
        float pi = Ps[(32 + hcl) * 33 + b]   + Ps[128 * 33 + (32 + hcl) * 33 + b];
        float pf = Ps[(64 + hcl) * 33 + b]   + Ps[128 * 33 + (64 + hcl) * 33 + b];
        float po = Ps[(96 + hcl) * 33 + b]   + Ps[128 * 33 + (96 + hcl) * 33 + b];
        size_t ci = (size_t)(jb + hcl) * Bsz + bbase + b;
        float cold = g_c[ci];
        float gg = tanhx(pg), ii = sigm(pi), ff = sigm(pf), oo = sigm(po);
        float cn = gg * ii + cold * ff;
        g_c[ci] = cn;
        float hv = tanhx(cn) * oo;
        float2 hh; hh.x = hv; hh.y = hv;
        *(float2*)&hout[(size_t)(jb + hcl) * 256 + (size_t)(bbase + b) * 2] = hh;
    }
}

// ---------------- phase 3: final projection + log_softmax ----------------
__global__ __launch_bounds__(256) void k_final(const float* __restrict__ Wph,
                                               const float* __restrict__ bp,
                                               float* __restrict__ out)
{
    __shared__ float hs[Hh];
    __shared__ float ls[Cc];
    __shared__ float red[256];
    int b = blockIdx.x, tid = threadIdx.x;
    const float* hT = g_h[Tt & 1];          // Tt even -> buffer 0
    for (int k = tid; k < Hh; k += 256) hs[k] = hT[(size_t)k * 256 + (size_t)b * 2];
    __syncthreads();

    float acc[4] = {0.f, 0.f, 0.f, 0.f};
    for (int k = 0; k < Hh; k++) {
        float hk = hs[k];
        const float* wrow = Wph + (size_t)k * Cc;
#pragma unroll
        for (int q = 0; q < 4; q++) {
            int n = tid + q * 256;
            if (n < Cc) acc[q] = fmaf(hk, wrow[n], acc[q]);
        }
    }
    float lmax = -1e30f;
#pragma unroll
    for (int q = 0; q < 4; q++) {
        int n = tid + q * 256;
        if (n < Cc) { float v = acc[q] + bp[n]; ls[n] = v; lmax = fmaxf(lmax, v); }
    }
    red[tid] = lmax; __syncthreads();
    for (int st = 128; st > 0; st >>= 1) {
        if (tid < st) red[tid] = fmaxf(red[tid], red[tid + st]);
        __syncthreads();
    }
    float mx = red[0]; __syncthreads();
    float lsum = 0.f;
#pragma unroll
    for (int q = 0; q < 4; q++) {
        int n = tid + q * 256;
        if (n < Cc) lsum += expf(ls[n] - mx);
    }
    red[tid] = lsum; __syncthreads();
    for (int st = 128; st > 0; st >>= 1) {
        if (tid < st) red[tid] += red[tid + st];
        __syncthreads();
    }
    float lse = logf(red[0]);
#pragma unroll
    for (int q = 0; q < 4; q++) {
        int n = tid + q * 256;
        if (n < Cc) out[(size_t)b * Cc + n] = ls[n] - mx - lse;
    }
}

// ---------------- launch ----------------
extern "C" void kernel_launch(void* const* d_in, const int* in_sizes, int n_in,
                              void* d_out, int out_size) {
    const float* x   = (const float*)d_in[0];
    const float* Wgx = (const float*)d_in[1];
    const float* Wix = (const float*)d_in[2];
    const float* Wfx = (const float*)d_in[3];
    const float* Wox = (const float*)d_in[4];
    const float* Wgh = (const float*)d_in[5];
    const float* Wih = (const float*)d_in[6];
    const float* Wfh = (const float*)d_in[7];
    const float* Woh = (const float*)d_in[8];
    const float* Wph = (const float*)d_in[9];
    const float* bg  = (const float*)d_in[10];
    const float* bi  = (const float*)d_in[11];
    const float* bf  = (const float*)d_in[12];
    const float* bo  = (const float*)d_in[13];
    const float* bp  = (const float*)d_in[14];
    float* out = (float*)d_out;

    // Not a stream operation; idempotent, graph-capture safe.
    cudaFuncSetAttribute(k_step, cudaFuncAttributeMaxDynamicSharedMemorySize,
                         STEP_SMEM_FLOATS * 4);

    k_init<<<(Hh * 256 + 255) / 256, 256>>>();
    k_input_proj<<<dim3(32, Tt), 256>>>(x, Wgx, Wix, Wfx, Wox, bg, bi, bf, bo);
    for (int s = 0; s < Tt; s++)
        k_step<<<dim3(4, 32), 256, STEP_SMEM_FLOATS * 4>>>(s, Wgh, Wih, Wfh, Woh);
    k_final<<<Bsz, 256>>>(Wph, bp, out);
}

// round 12
// speedup vs baseline: 3.8055x; 3.8055x over previous
#include <cuda_runtime.h>
#include <cuda_bf16.h>
#include <cstdint>
#include <cstddef>

#define Bsz 128
#define Tt  256
#define Dd  256
#define Hh  1024
#define Cc  1000
#define NCH 16

__device__ float g_xproj[(size_t)Tt * 32 * 128 * 128];   // [t][j][n128][b]
__device__ char  g_wt[(size_t)128 * 2 * NCH * 4096];     // W tiles [J][term][q][n32][k64]
__device__ char  g_ht[(size_t)2 * 2 * NCH * 16384];      // h tiles [ping][term][q][b128][k64]
__device__ float g_c[(size_t)Hh * Bsz];                  // c [hcol][b]
__device__ float g_hp[(size_t)Hh * Bsz];                 // fp32 h for k_final

__device__ __forceinline__ unsigned long long pack2(float lo, float hi) {
    unsigned long long r; asm("mov.b64 %0, {%1, %2};" : "=l"(r) : "f"(lo), "f"(hi)); return r;
}
__device__ __forceinline__ void fma2(unsigned long long &a, unsigned long long x, unsigned long long y) {
    asm("fma.rn.f32x2 %0, %1, %2, %0;" : "+l"(a) : "l"(x), "l"(y));
}
__device__ __forceinline__ float sigm(float x) { return __fdividef(1.f, 1.f + __expf(-x)); }
__device__ __forceinline__ float tanhx(float x) { return 1.f - __fdividef(2.f, __expf(2.f * x) + 1.f); }
__device__ __forceinline__ void cpa16(uint32_t d, const void* s) {
    asm volatile("cp.async.cg.shared.global [%0], [%1], 16;" :: "r"(d), "l"(s));
}
#define CPA_COMMIT() asm volatile("cp.async.commit_group;")
#define CPA_WAIT0()  asm volatile("cp.async.wait_group 0;")
#define SWZ(off) ((off) ^ (((off) >> 3) & 0x70))

__device__ __forceinline__ uint32_t smem_u32(const void* p) {
    uint32_t a; asm("{ .reg .u64 t; cvta.to.shared.u64 t, %1; cvt.u32.u64 %0, t; }" : "=r"(a) : "l"(p)); return a;
}
__device__ __forceinline__ void ldsm4(uint32_t* r, uint32_t a) {
    asm volatile("ldmatrix.sync.aligned.m8n8.x4.shared.b16 {%0,%1,%2,%3}, [%4];"
        : "=r"(r[0]), "=r"(r[1]), "=r"(r[2]), "=r"(r[3]) : "r"(a));
}
__device__ __forceinline__ void ldsm2(uint32_t* r, uint32_t a) {
    asm volatile("ldmatrix.sync.aligned.m8n8.x2.shared.b16 {%0,%1}, [%2];"
        : "=r"(r[0]), "=r"(r[1]) : "r"(a));
}
__device__ __forceinline__ void mma16816(float* d, const uint32_t* a, const uint32_t* b) {
    asm volatile("mma.sync.aligned.m16n8k16.row.col.f32.bf16.bf16.f32 "
        "{%0,%1,%2,%3}, {%4,%5,%6,%7}, {%8,%9}, {%0,%1,%2,%3};"
        : "+f"(d[0]), "+f"(d[1]), "+f"(d[2]), "+f"(d[3])
        : "r"(a[0]), "r"(a[1]), "r"(a[2]), "r"(a[3]), "r"(b[0]), "r"(b[1]));
}

__global__ void k_init() {
    int i = blockIdx.x * blockDim.x + threadIdx.x;
    if (i < 131072) { ((uint32_t*)g_ht)[i] = 0u; g_c[i] = 0.f; }  // ping0 tiles + c
}

// W tiles: [J][term][q][n'32][k64] bf16 swizzled; n' = hcl*4+gate, col = J*8+hcl
__global__ __launch_bounds__(128) void k_prep(
    const float* __restrict__ Wg, const float* __restrict__ Wi,
    const float* __restrict__ Wf, const float* __restrict__ Wo)
{
    int J = blockIdx.x >> 4, q = blockIdx.x & 15;
    char* b0 = g_wt + (size_t)((J * 2 + 0) * NCH + q) * 4096;
    char* b1 = g_wt + (size_t)((J * 2 + 1) * NCH + q) * 4096;
    for (int g = threadIdx.x; g < 256; g += 128) {
        int np = g >> 3, k8 = g & 7;
        int gate = np & 3, hcol = J * 8 + (np >> 2);
        const float* W = (gate < 2) ? (gate == 0 ? Wg : Wi) : (gate == 2 ? Wf : Wo);
        alignas(16) __nv_bfloat16 h8[8], l8[8];
#pragma unroll
        for (int i = 0; i < 8; i++) {
            float w = W[(size_t)(q * 64 + k8 * 8 + i) * Hh + hcol];
            __nv_bfloat16 h = __float2bfloat16(w);
            h8[i] = h; l8[i] = __float2bfloat16(w - __bfloat162float(h));
        }
        uint32_t off = SWZ((uint32_t)(np * 128 + k8 * 16));
        *(uint4*)(b0 + off) = *(uint4*)h8;
        *(uint4*)(b1 + off) = *(uint4*)l8;
    }
}

// phase 1: proven FFMA GEMM, xproj [t][j][n128=gate*32+hcl32][b]
__global__ __launch_bounds__(256, 2) void k_input_proj(
    const float* __restrict__ x,
    const float* __restrict__ Wg, const float* __restrict__ Wi,
    const float* __restrict__ Wf, const float* __restrict__ Wo,
    const float* __restrict__ bg, const float* __restrict__ bi,
    const float* __restrict__ bf, const float* __restrict__ bo)
{
    __shared__ float Ws[32][128];
    __shared__ float Xs[32][132];
    int j = blockIdx.x, t = blockIdx.y;
    int tid = threadIdx.x;
    int tn = tid & 15, tb = tid >> 4;
    int n0 = tn * 8, b0 = tb * 8;
    int jb = j * 32;
    int c4w = tid & 31, gatew = c4w >> 3;
    const float* Wsel = (gatew < 2) ? (gatew == 0 ? Wg : Wi) : (gatew == 2 ? Wf : Wo);
    const float* wsrc0 = Wsel + jb + (c4w & 7) * 4;
    unsigned long long acc[32];
#pragma unroll
    for (int q = 0; q < 32; q++) acc[q] = 0ull;
    for (int kc = 0; kc < Dd / 32; kc++) {
        int k0 = kc * 32;
#pragma unroll
        for (int p = 0; p < 4; p++) {
            int row = p * 8 + (tid >> 5);
            *(float4*)&Ws[row][c4w * 4] = *(const float4*)(wsrc0 + (size_t)(k0 + row) * Hh);
        }
#pragma unroll
        for (int p = 0; p < 4; p++) {
            int fi = p * 256 + tid, b = fi >> 3, d4 = fi & 7;
            float4 v = *(const float4*)&x[((size_t)b * Tt + t) * Dd + k0 + d4 * 4];
            Xs[d4 * 4 + 0][b] = v.x; Xs[d4 * 4 + 1][b] = v.y;
            Xs[d4 * 4 + 2][b] = v.z; Xs[d4 * 4 + 3][b] = v.w;
        }
        __syncthreads();
#pragma unroll 4
        for (int kr = 0; kr < 32; kr++) {
            float4 wA = *(const float4*)&Ws[kr][n0];
            float4 wB = *(const float4*)&Ws[kr][n0 + 4];
            float4 xA = *(const float4*)&Xs[kr][b0];
            float4 xB = *(const float4*)&Xs[kr][b0 + 4];
            unsigned long long w0 = pack2(wA.x, wA.y), w1 = pack2(wA.z, wA.w);
            unsigned long long w2 = pack2(wB.x, wB.y), w3 = pack2(wB.z, wB.w);
            float xv[8] = {xA.x, xA.y, xA.z, xA.w, xB.x, xB.y, xB.z, xB.w};
#pragma unroll
            for (int b = 0; b < 8; b++) {
                unsigned long long xb = pack2(xv[b], xv[b]);
                fma2(acc[0 * 8 + b], w0, xb); fma2(acc[1 * 8 + b], w1, xb);
                fma2(acc[2 * 8 + b], w2, xb); fma2(acc[3 * 8 + b], w3, xb);
            }
        }
        __syncthreads();
    }
    float* outp = g_xproj + (((size_t)t * 32 + j) * 128) * 128;
    int gate = n0 >> 5;
    const float* bsel = (gate < 2) ? (gate == 0 ? bg : bi) : (gate == 2 ? bf : bo);
#pragma unroll
    for (int np = 0; np < 4; np++) {
        int n = n0 + 2 * np;
        float bia0 = bsel[jb + (n & 31)], bia1 = bsel[jb + ((n + 1) & 31)];
#pragma unroll
        for (int b = 0; b < 8; b++) {
            float2 v = *(float2*)&acc[np * 8 + b];
            outp[(size_t)n * 128 + b0 + b]       = v.x + bia0;
            outp[(size_t)(n + 1) * 128 + b0 + b] = v.y + bia1;
        }
    }
}

// phase 2: HMMA step. grid 128 (J), 256 thr (8 warps: wm=wid&3, wn=wid>>2).
// smem: Ahi[2buf 16K] | Alo[2buf 16K] | Bhi[2buf 4K] | Blo[2buf 4K] = 80K
#define STEP_SMEM 81920
__global__ __launch_bounds__(256, 1) void k_step_hmma(int s)
{
    extern __shared__ __align__(1024) char smx[];
    uint32_t sb = smem_u32(smx);
    int tid = threadIdx.x, wid = tid >> 5, lane = tid & 31;
    int wm = wid & 3, wn = wid >> 2;
    int J = blockIdx.x;
    int pin = s & 1, pout = (s + 1) & 1;

    const char* gAh = g_ht + (size_t)(pin * 2 + 0) * NCH * 16384;
    const char* gAl = g_ht + (size_t)(pin * 2 + 1) * NCH * 16384;
    const char* gBh = g_wt + (size_t)(J * 2 + 0) * NCH * 4096;
    const char* gBl = g_wt + (size_t)(J * 2 + 1) * NCH * 4096;

    float d[16];
#pragma unroll
    for (int q = 0; q < 16; q++) d[q] = 0.f;

    // prefetch chunk 0 into buf 0
    {
#pragma unroll
        for (int p = 0; p < 4; p++) {
            int g = p * 256 + tid;
            cpa16(sb + g * 16, gAh + g * 16);
            cpa16(sb + 32768 + g * 16, gAl + g * 16);
        }
        cpa16(sb + 65536 + tid * 16, gBh + tid * 16);
        cpa16(sb + 73728 + tid * 16, gBl + tid * 16);
        CPA_COMMIT();
    }

    int buf = 0;
    for (int q = 0; q < NCH; q++) {
        CPA_WAIT0();
        __syncthreads();
        if (q < 15) {
            const char* ah = gAh + (size_t)(q + 1) * 16384;
            const char* al = gAl + (size_t)(q + 1) * 16384;
            const char* bh = gBh + (size_t)(q + 1) * 4096;
            const char* bl = gBl + (size_t)(q + 1) * 4096;
            uint32_t o = (buf ^ 1) ? 16384u : 0u;
            uint32_t ob = (buf ^ 1) ? 4096u : 0u;
#pragma unroll
            for (int p = 0; p < 4; p++) {
                int g = p * 256 + tid;
                cpa16(sb + o + g * 16, ah + g * 16);
                cpa16(sb + 32768 + o + g * 16, al + g * 16);
            }
            cpa16(sb + 65536 + ob + tid * 16, bh + tid * 16);
            cpa16(sb + 73728 + ob + tid * 16, bl + tid * 16);
            CPA_COMMIT();
        }
        uint32_t aAh = sb + buf * 16384;
        uint32_t aAl = sb + 32768 + buf * 16384;
        uint32_t aBh = sb + 65536 + buf * 4096;
        uint32_t aBl = sb + 73728 + buf * 4096;
        int selA = lane >> 3;
        int rowA = (lane & 7) + (selA & 1) * 8;
        int kcA = (selA >> 1) * 8;
        int rowB = lane & 7;
        int kcB = ((lane >> 3) & 1) * 8;
#pragma unroll
        for (int ks = 0; ks < 4; ks++) {
            uint32_t Ah[2][4], Al[2][4], Bh[2][2], Bl[2][2];
#pragma unroll
            for (int mb = 0; mb < 2; mb++) {
                uint32_t offA = SWZ((uint32_t)((wm * 32 + mb * 16 + rowA) * 128 + (ks * 16 + kcA) * 2));
                ldsm4(Ah[mb], aAh + offA);
                ldsm4(Al[mb], aAl + offA);
            }
#pragma unroll
            for (int nb = 0; nb < 2; nb++) {
                uint32_t offB = SWZ((uint32_t)((wn * 16 + nb * 8 + rowB) * 128 + (ks * 16 + kcB) * 2));
                ldsm2(Bh[nb], aBh + offB);
                ldsm2(Bl[nb], aBl + offB);
            }
#pragma unroll
            for (int mb = 0; mb < 2; mb++)
#pragma unroll
                for (int nb = 0; nb < 2; nb++) {
                    float* dd = d + (mb * 2 + nb) * 4;
                    mma16816(dd, Ah[mb], Bh[nb]);
                    mma16816(dd, Ah[mb], Bl[nb]);
                    mma16816(dd, Al[mb], Bh[nb]);
                }
        }
        buf ^= 1;
        if (q < 15) __syncthreads();
    }
    __syncthreads();

    // dump D to Ps[128][33]
    float* Ps = (float*)smx;
    int r = lane >> 2, c = (lane & 3) * 2;
#pragma unroll
    for (int mb = 0; mb < 2; mb++)
#pragma unroll
        for (int nb = 0; nb < 2; nb++) {
            float* dd = d + (mb * 2 + nb) * 4;
            int m = wm * 32 + mb * 16 + r, n = wn * 16 + nb * 8 + c;
            Ps[m * 33 + n] = dd[0];       Ps[m * 33 + n + 1] = dd[1];
            Ps[(m + 8) * 33 + n] = dd[2]; Ps[(m + 8) * 33 + n + 1] = dd[3];
        }
    __syncthreads();

    // gate fusion: thread -> b = tid&127, hcl half = tid>>7
    __nv_bfloat16* Hhi = (__nv_bfloat16*)(smx + 17408);
    __nv_bfloat16* Hlo = (__nv_bfloat16*)(smx + 19456);
    int b = tid & 127, hh4 = (tid >> 7) * 4;
#pragma unroll
    for (int e = 0; e < 4; e++) {
        int hcl = hh4 + e;
        int hcg = J * 8 + hcl;
        int j = hcg >> 5, r32 = hcg & 31;
        const float* xp = g_xproj + (((size_t)s * 32 + j) * 128 + r32) * 128 + b;
        float pg = Ps[b * 33 + hcl * 4 + 0] + xp[0];
        float pi = Ps[b * 33 + hcl * 4 + 1] + xp[32 * 128];
        float pf = Ps[b * 33 + hcl * 4 + 2] + xp[64 * 128];
        float po = Ps[b * 33 + hcl * 4 + 3] + xp[96 * 128];
        size_t ci = (size_t)hcg * Bsz + b;
        float gg = tanhx(pg), ii = sigm(pi), ff = sigm(pf), oo = sigm(po);
        float cn = gg * ii + g_c[ci] * ff;
        g_c[ci] = cn;
        float hv = tanhx(cn) * oo;
        g_hp[ci] = hv;
        __nv_bfloat16 hb = __float2bfloat16(hv);
        Hhi[b * 8 + hcl] = hb;
        Hlo[b * 8 + hcl] = __float2bfloat16(hv - __bfloat162float(hb));
    }
    __syncthreads();

    // store h tiles: 16B per b per term, swizzled
    {
        int bb = tid & 127, term = tid >> 7;
        int q = J >> 3;
        uint32_t off = SWZ((uint32_t)(bb * 128 + (J & 7) * 16));
        char* dst = g_ht + (size_t)((pout * 2 + term) * NCH + q) * 16384 + off;
        const __nv_bfloat16* src = term ? Hlo : Hhi;
        *(uint4*)dst = *(const uint4*)&src[bb * 8];
    }
}

// phase 3
__global__ __launch_bounds__(256) void k_final(const float* __restrict__ Wph,
                                               const float* __restrict__ bp,
                                               float* __restrict__ out)
{
    __shared__ float hs[Hh];
    __shared__ float ls[Cc];
    __shared__ float red[256];
    int b = blockIdx.x, tid = threadIdx.x;
    for (int k = tid; k < Hh; k += 256) hs[k] = g_hp[(size_t)k * Bsz + b];
    __syncthreads();
    float acc[4] = {0.f, 0.f, 0.f, 0.f};
    for (int k = 0; k < Hh; k++) {
        float hk = hs[k];
        const float* wr = Wph + (size_t)k * Cc;
#pragma unroll
        for (int q = 0; q < 4; q++) { int n = tid + q * 256; if (n < Cc) acc[q] = fmaf(hk, wr[n], acc[q]); }
    }
    float lmax = -1e30f;
#pragma unroll
    for (int q = 0; q < 4; q++) { int n = tid + q * 256; if (n < Cc) { float v = acc[q] + bp[n]; ls[n] = v; lmax = fmaxf(lmax, v); } }
    red[tid] = lmax; __syncthreads();
    for (int st = 128; st > 0; st >>= 1) { if (tid < st) red[tid] = fmaxf(red[tid], red[tid + st]); __syncthreads(); }
    float mx = red[0]; __syncthreads();
    float lsum = 0.f;
#pragma unroll
    for (int q = 0; q < 4; q++) { int n = tid + q * 256; if (n < Cc) lsum += expf(ls[n] - mx); }
    red[tid] = lsum; __syncthreads();
    for (int st = 128; st > 0; st >>= 1) { if (tid < st) red[tid] += red[tid + st]; __syncthreads(); }
    float lse = logf(red[0]);
#pragma unroll
    for (int q = 0; q < 4; q++) { int n = tid + q * 256; if (n < Cc) out[(size_t)b * Cc + n] = ls[n] - mx - lse; }
}

extern "C" void kernel_launch(void* const* d_in, const int* in_sizes, int n_in,
                              void* d_out, int out_size) {
    const float* x   = (const float*)d_in[0];
    const float* Wgx = (const float*)d_in[1];
    const float* Wix = (const float*)d_in[2];
    const float* Wfx = (const float*)d_in[3];
    const float* Wox = (const float*)d_in[4];
    const float* Wgh = (const float*)d_in[5];
    const float* Wih = (const float*)d_in[6];
    const float* Wfh = (const float*)d_in[7];
    const float* Woh = (const float*)d_in[8];
    const float* Wph = (const float*)d_in[9];
    const float* bg  = (const float*)d_in[10];
    const float* bi  = (const float*)d_in[11];
    const float* bf  = (const float*)d_in[12];
    const float* bo  = (const float*)d_in[13];
    const float* bp  = (const float*)d_in[14];
    float* out = (float*)d_out;

    cudaFuncSetAttribute(k_step_hmma, cudaFuncAttributeMaxDynamicSharedMemorySize, STEP_SMEM);

    k_init<<<512, 256>>>();
    k_prep<<<128 * 16, 128>>>(Wgh, Wih, Wfh, Woh);
    k_input_proj<<<dim3(32, Tt), 256>>>(x, Wgx, Wix, Wfx, Wox, bg, bi, bf, bo);
    for (int s = 0; s < Tt; s++)
        k_step_hmma<<<128, 256, STEP_SMEM>>>(s);
    k_final<<<Bsz, 256>>>(Wph, bp, out);
}

// round 13
// speedup vs baseline: 3.8647x; 1.0155x over previous
#include <cuda_runtime.h>
#include <cuda_bf16.h>
#include <cstdint>
#include <cstddef>

#define Bsz 128
#define Tt  256
#define Dd  256
#define Hh  1024
#define Cc  1000
#define NCH 16

__device__ float g_xproj[(size_t)Tt * 32 * 128 * 128];   // [t][j][n128][b]
__device__ char  g_wt[(size_t)128 * 2 * NCH * 4096];     // W tiles [J][term][q][n32][k64]
__device__ char  g_ht[(size_t)2 * 2 * NCH * 16384];      // h tiles [ping][term][q][b128][k64]
__device__ float g_c[(size_t)Hh * Bsz];                  // c [hcol][b]
__device__ float g_hp[(size_t)Hh * Bsz];                 // fp32 h for k_final

__device__ __forceinline__ unsigned long long pack2(float lo, float hi) {
    unsigned long long r; asm("mov.b64 %0, {%1, %2};" : "=l"(r) : "f"(lo), "f"(hi)); return r;
}
__device__ __forceinline__ void fma2(unsigned long long &a, unsigned long long x, unsigned long long y) {
    asm("fma.rn.f32x2 %0, %1, %2, %0;" : "+l"(a) : "l"(x), "l"(y));
}
__device__ __forceinline__ float sigm(float x) { return __fdividef(1.f, 1.f + __expf(-x)); }
__device__ __forceinline__ float tanhx(float x) { return 1.f - __fdividef(2.f, __expf(2.f * x) + 1.f); }
__device__ __forceinline__ void cpa16(uint32_t d, const void* s) {
    asm volatile("cp.async.cg.shared.global [%0], [%1], 16;" :: "r"(d), "l"(s));
}
#define CPA_COMMIT() asm volatile("cp.async.commit_group;")
#define SWZ(off) ((off) ^ (((off) >> 3) & 0x70))

__device__ __forceinline__ uint32_t smem_u32(const void* p) {
    uint32_t a; asm("{ .reg .u64 t; cvta.to.shared.u64 t, %1; cvt.u32.u64 %0, t; }" : "=r"(a) : "l"(p)); return a;
}
__device__ __forceinline__ void ldsm4(uint32_t* r, uint32_t a) {
    asm volatile("ldmatrix.sync.aligned.m8n8.x4.shared.b16 {%0,%1,%2,%3}, [%4];"
        : "=r"(r[0]), "=r"(r[1]), "=r"(r[2]), "=r"(r[3]) : "r"(a));
}
__device__ __forceinline__ void ldsm2(uint32_t* r, uint32_t a) {
    asm volatile("ldmatrix.sync.aligned.m8n8.x2.shared.b16 {%0,%1}, [%2];"
        : "=r"(r[0]), "=r"(r[1]) : "r"(a));
}
__device__ __forceinline__ void mma16816(float* d, const uint32_t* a, const uint32_t* b) {
    asm volatile("mma.sync.aligned.m16n8k16.row.col.f32.bf16.bf16.f32 "
        "{%0,%1,%2,%3}, {%4,%5,%6,%7}, {%8,%9}, {%0,%1,%2,%3};"
        : "+f"(d[0]), "+f"(d[1]), "+f"(d[2]), "+f"(d[3])
        : "r"(a[0]), "r"(a[1]), "r"(a[2]), "r"(a[3]), "r"(b[0]), "r"(b[1]));
}

__global__ void k_init() {
    int i = blockIdx.x * blockDim.x + threadIdx.x;
    if (i < 131072) { ((uint32_t*)g_ht)[i] = 0u; g_c[i] = 0.f; }  // ping0 tiles + c
}

// W tiles: [J][term][q][n'32][k64] bf16 swizzled; n' = hcl*4+gate, col = J*8+hcl
__global__ __launch_bounds__(128) void k_prep(
    const float* __restrict__ Wg, const float* __restrict__ Wi,
    const float* __restrict__ Wf, const float* __restrict__ Wo)
{
    int J = blockIdx.x >> 4, q = blockIdx.x & 15;
    char* b0 = g_wt + (size_t)((J * 2 + 0) * NCH + q) * 4096;
    char* b1 = g_wt + (size_t)((J * 2 + 1) * NCH + q) * 4096;
    for (int g = threadIdx.x; g < 256; g += 128) {
        int np = g >> 3, k8 = g & 7;
        int gate = np & 3, hcol = J * 8 + (np >> 2);
        const float* W = (gate < 2) ? (gate == 0 ? Wg : Wi) : (gate == 2 ? Wf : Wo);
        alignas(16) __nv_bfloat16 h8[8], l8[8];
#pragma unroll
        for (int i = 0; i < 8; i++) {
            float w = W[(size_t)(q * 64 + k8 * 8 + i) * Hh + hcol];
            __nv_bfloat16 h = __float2bfloat16(w);
            h8[i] = h; l8[i] = __float2bfloat16(w - __bfloat162float(h));
        }
        uint32_t off = SWZ((uint32_t)(np * 128 + k8 * 16));
        *(uint4*)(b0 + off) = *(uint4*)h8;
        *(uint4*)(b1 + off) = *(uint4*)l8;
    }
}

// phase 1: proven FFMA GEMM, xproj [t][j][n128=gate*32+hcl32][b]
__global__ __launch_bounds__(256, 2) void k_input_proj(
    const float* __restrict__ x,
    const float* __restrict__ Wg, const float* __restrict__ Wi,
    const float* __restrict__ Wf, const float* __restrict__ Wo,
    const float* __restrict__ bg, const float* __restrict__ bi,
    const float* __restrict__ bf, const float* __restrict__ bo)
{
    __shared__ float Ws[32][128];
    __shared__ float Xs[32][132];
    int j = blockIdx.x, t = blockIdx.y;
    int tid = threadIdx.x;
    int tn = tid & 15, tb = tid >> 4;
    int n0 = tn * 8, b0 = tb * 8;
    int jb = j * 32;
    int c4w = tid & 31, gatew = c4w >> 3;
    const float* Wsel = (gatew < 2) ? (gatew == 0 ? Wg : Wi) : (gatew == 2 ? Wf : Wo);
    const float* wsrc0 = Wsel + jb + (c4w & 7) * 4;
    unsigned long long acc[32];
#pragma unroll
    for (int q = 0; q < 32; q++) acc[q] = 0ull;
    for (int kc = 0; kc < Dd / 32; kc++) {
        int k0 = kc * 32;
#pragma unroll
        for (int p = 0; p < 4; p++) {
            int row = p * 8 + (tid >> 5);
            *(float4*)&Ws[row][c4w * 4] = *(const float4*)(wsrc0 + (size_t)(k0 + row) * Hh);
        }
#pragma unroll
        for (int p = 0; p < 4; p++) {
            int fi = p * 256 + tid, b = fi >> 3, d4 = fi & 7;
            float4 v = *(const float4*)&x[((size_t)b * Tt + t) * Dd + k0 + d4 * 4];
            Xs[d4 * 4 + 0][b] = v.x; Xs[d4 * 4 + 1][b] = v.y;
            Xs[d4 * 4 + 2][b] = v.z; Xs[d4 * 4 + 3][b] = v.w;
        }
        __syncthreads();
#pragma unroll 4
        for (int kr = 0; kr < 32; kr++) {
            float4 wA = *(const float4*)&Ws[kr][n0];
            float4 wB = *(const float4*)&Ws[kr][n0 + 4];
            float4 xA = *(const float4*)&Xs[kr][b0];
            float4 xB = *(const float4*)&Xs[kr][b0 + 4];
            unsigned long long w0 = pack2(wA.x, wA.y), w1 = pack2(wA.z, wA.w);
            unsigned long long w2 = pack2(wB.x, wB.y), w3 = pack2(wB.z, wB.w);
            float xv[8] = {xA.x, xA.y, xA.z, xA.w, xB.x, xB.y, xB.z, xB.w};
#pragma unroll
            for (int b = 0; b < 8; b++) {
                unsigned long long xb = pack2(xv[b], xv[b]);
                fma2(acc[0 * 8 + b], w0, xb); fma2(acc[1 * 8 + b], w1, xb);
                fma2(acc[2 * 8 + b], w2, xb); fma2(acc[3 * 8 + b], w3, xb);
            }
        }
        __syncthreads();
    }
    float* outp = g_xproj + (((size_t)t * 32 + j) * 128) * 128;
    int gate = n0 >> 5;
    const float* bsel = (gate < 2) ? (gate == 0 ? bg : bi) : (gate == 2 ? bf : bo);
#pragma unroll
    for (int np = 0; np < 4; np++) {
        int n = n0 + 2 * np;
        float bia0 = bsel[jb + (n & 31)], bia1 = bsel[jb + ((n + 1) & 31)];
#pragma unroll
        for (int b = 0; b < 8; b++) {
            float2 v = *(float2*)&acc[np * 8 + b];
            outp[(size_t)n * 128 + b0 + b]       = v.x + bia0;
            outp[(size_t)(n + 1) * 128 + b0 + b] = v.y + bia1;
        }
    }
}

// phase 2: HMMA step, 4-deep chunk pipeline. grid 128 (J), 256 thr (8 warps).
// smem: 4 bufs x 40KB {Ahi 16K | Alo 16K | Bhi 4K | Blo 4K} = 160 KB
#define BUFSZ 40960
#define STEP_SMEM (4 * BUFSZ)
__global__ __launch_bounds__(256, 1) void k_step_hmma(int s)
{
    extern __shared__ __align__(1024) char smx[];
    uint32_t sb = smem_u32(smx);
    int tid = threadIdx.x, wid = tid >> 5, lane = tid & 32 - 1;
    int wm = wid & 3, wn = wid >> 2;
    int J = blockIdx.x;
    int pin = s & 1, pout = (s + 1) & 1;

    const char* gAh = g_ht + (size_t)(pin * 2 + 0) * NCH * 16384;
    const char* gAl = g_ht + (size_t)(pin * 2 + 1) * NCH * 16384;
    const char* gBh = g_wt + (size_t)(J * 2 + 0) * NCH * 4096;
    const char* gBl = g_wt + (size_t)(J * 2 + 1) * NCH * 4096;

    float d[16];
#pragma unroll
    for (int q = 0; q < 16; q++) d[q] = 0.f;

    // prefetch chunks 0..2 into bufs 0..2 (3 groups in flight)
#pragma unroll
    for (int q0 = 0; q0 < 3; q0++) {
        uint32_t bs = sb + q0 * BUFSZ;
        const char* ah = gAh + (size_t)q0 * 16384;
        const char* al = gAl + (size_t)q0 * 16384;
#pragma unroll
        for (int p = 0; p < 4; p++) {
            int g = p * 256 + tid;
            cpa16(bs + g * 16, ah + g * 16);
            cpa16(bs + 16384 + g * 16, al + g * 16);
        }
        cpa16(bs + 32768 + tid * 16, gBh + (size_t)q0 * 4096 + tid * 16);
        cpa16(bs + 36864 + tid * 16, gBl + (size_t)q0 * 4096 + tid * 16);
        CPA_COMMIT();
    }

    int selA = lane >> 3;
    int rowA = (lane & 7) + (selA & 1) * 8;
    int kcA = (selA >> 1) * 8;
    int rowB = lane & 7;
    int kcB = ((lane >> 3) & 1) * 8;

    for (int q = 0; q < NCH; q++) {
        asm volatile("cp.async.wait_group 2;");   // chunk q's group retired
        __syncthreads();
        uint32_t bs = sb + (q & 3) * BUFSZ;
        uint32_t aAh = bs, aAl = bs + 16384, aBh = bs + 32768, aBl = bs + 36864;
#pragma unroll
        for (int ks = 0; ks < 4; ks++) {
            uint32_t Ah[2][4], Al[2][4], Bh[2][2], Bl[2][2];
#pragma unroll
            for (int mb = 0; mb < 2; mb++) {
                uint32_t offA = SWZ((uint32_t)((wm * 32 + mb * 16 + rowA) * 128 + (ks * 16 + kcA) * 2));
                ldsm4(Ah[mb], aAh + offA);
                ldsm4(Al[mb], aAl + offA);
            }
#pragma unroll
            for (int nb = 0; nb < 2; nb++) {
                uint32_t offB = SWZ((uint32_t)((wn * 16 + nb * 8 + rowB) * 128 + (ks * 16 + kcB) * 2));
                ldsm2(Bh[nb], aBh + offB);
                ldsm2(Bl[nb], aBl + offB);
            }
#pragma unroll
            for (int mb = 0; mb < 2; mb++)
#pragma unroll
                for (int nb = 0; nb < 2; nb++) {
                    float* dd = d + (mb * 2 + nb) * 4;
                    mma16816(dd, Ah[mb], Bh[nb]);
                    mma16816(dd, Ah[mb], Bl[nb]);
                    mma16816(dd, Al[mb], Bh[nb]);
                }
        }
        __syncthreads();
        if (q + 3 < NCH) {    // refill this buffer's successor (chunk q+3 -> buf (q+3)&3)
            int qn = q + 3;
            uint32_t bn = sb + (qn & 3) * BUFSZ;
            const char* ah = gAh + (size_t)qn * 16384;
            const char* al = gAl + (size_t)qn * 16384;
#pragma unroll
            for (int p = 0; p < 4; p++) {
                int g = p * 256 + tid;
                cpa16(bn + g * 16, ah + g * 16);
                cpa16(bn + 16384 + g * 16, al + g * 16);
            }
            cpa16(bn + 32768 + tid * 16, gBh + (size_t)qn * 4096 + tid * 16);
            cpa16(bn + 36864 + tid * 16, gBl + (size_t)qn * 4096 + tid * 16);
            CPA_COMMIT();
        }
    }
    __syncthreads();

    // dump D to Ps[128][33]
    float* Ps = (float*)smx;
    int r = lane >> 2, c = (lane & 3) * 2;
#pragma unroll
    for (int mb = 0; mb < 2; mb++)
#pragma unroll
        for (int nb = 0; nb < 2; nb++) {
            float* dd = d + (mb * 2 + nb) * 4;
            int m = wm * 32 + mb * 16 + r, n = wn * 16 + nb * 8 + c;
            Ps[m * 33 + n] = dd[0];       Ps[m * 33 + n + 1] = dd[1];
            Ps[(m + 8) * 33 + n] = dd[2]; Ps[(m + 8) * 33 + n + 1] = dd[3];
        }
    __syncthreads();

    // gate fusion: thread -> b = tid&127, hcl half = tid>>7
    __nv_bfloat16* Hhi = (__nv_bfloat16*)(smx + 17408);
    __nv_bfloat16* Hlo = (__nv_bfloat16*)(smx + 19456);
    int b = tid & 127, hh4 = (tid >> 7) * 4;
#pragma unroll
    for (int e = 0; e < 4; e++) {
        int hcl = hh4 + e;
        int hcg = J * 8 + hcl;
        int j = hcg >> 5, r32 = hcg & 31;
        const float* xp = g_xproj + (((size_t)s * 32 + j) * 128 + r32) * 128 + b;
        float pg = Ps[b * 33 + hcl * 4 + 0] + xp[0];
        float pi = Ps[b * 33 + hcl * 4 + 1] + xp[32 * 128];
        float pf = Ps[b * 33 + hcl * 4 + 2] + xp[64 * 128];
        float po = Ps[b * 33 + hcl * 4 + 3] + xp[96 * 128];
        size_t ci = (size_t)hcg * Bsz + b;
        float gg = tanhx(pg), ii = sigm(pi), ff = sigm(pf), oo = sigm(po);
        float cn = gg * ii + g_c[ci] * ff;
        g_c[ci] = cn;
        float hv = tanhx(cn) * oo;
        g_hp[ci] = hv;
        __nv_bfloat16 hb = __float2bfloat16(hv);
        Hhi[b * 8 + hcl] = hb;
        Hlo[b * 8 + hcl] = __float2bfloat16(hv - __bfloat162float(hb));
    }
    __syncthreads();

    // store h tiles: 16B per b per term, swizzled
    {
        int bb = tid & 127, term = tid >> 7;
        int q = J >> 3;
        uint32_t off = SWZ((uint32_t)(bb * 128 + (J & 7) * 16));
        char* dst = g_ht + (size_t)((pout * 2 + term) * NCH + q) * 16384 + off;
        const __nv_bfloat16* src = term ? Hlo : Hhi;
        *(uint4*)dst = *(const uint4*)&src[bb * 8];
    }
}

// phase 3
__global__ __launch_bounds__(256) void k_final(const float* __restrict__ Wph,
                                               const float* __restrict__ bp,
                                               float* __restrict__ out)
{
    __shared__ float hs[Hh];
    __shared__ float ls[Cc];
    __shared__ float red[256];
    int b = blockIdx.x, tid = threadIdx.x;
    for (int k = tid; k < Hh; k += 256) hs[k] = g_hp[(size_t)k * Bsz + b];
    __syncthreads();
    float acc[4] = {0.f, 0.f, 0.f, 0.f};
    for (int k = 0; k < Hh; k++) {
        float hk = hs[k];
        const float* wr = Wph + (size_t)k * Cc;
#pragma unroll
        for (int q = 0; q < 4; q++) { int n = tid + q * 256; if (n < Cc) acc[q] = fmaf(hk, wr[n], acc[q]); }
    }
    float lmax = -1e30f;
#pragma unroll
    for (int q = 0; q < 4; q++) { int n = tid + q * 256; if (n < Cc) { float v = acc[q] + bp[n]; ls[n] = v; lmax = fmaxf(lmax, v); } }
    red[tid] = lmax; __syncthreads();
    for (int st = 128; st > 0; st >>= 1) { if (tid < st) red[tid] = fmaxf(red[tid], red[tid + st]); __syncthreads(); }
    float mx = red[0]; __syncthreads();
    float lsum = 0.f;
#pragma unroll
    for (int q = 0; q < 4; q++) { int n = tid + q * 256; if (n < Cc) lsum += expf(ls[n] - mx); }
    red[tid] = lsum; __syncthreads();
    for (int st = 128; st > 0; st >>= 1) { if (tid < st) red[tid] += red[tid + st]; __syncthreads(); }
    float lse = logf(red[0]);
#pragma unroll
    for (int q = 0; q < 4; q++) { int n = tid + q * 256; if (n < Cc) out[(size_t)b * Cc + n] = ls[n] - mx - lse; }
}

extern "C" void kernel_launch(void* const* d_in, const int* in_sizes, int n_in,
                              void* d_out, int out_size) {
    const float* x   = (const float*)d_in[0];
    const float* Wgx = (const float*)d_in[1];
    const float* Wix = (const float*)d_in[2];
    const float* Wfx = (const float*)d_in[3];
    const float* Wox = (const float*)d_in[4];
    const float* Wgh = (const float*)d_in[5];
    const float* Wih = (const float*)d_in[6];
    const float* Wfh = (const float*)d_in[7];
    const float* Woh = (const float*)d_in[8];
    const float* Wph = (const float*)d_in[9];
    const float* bg  = (const float*)d_in[10];
    const float* bi  = (const float*)d_in[11];
    const float* bf  = (const float*)d_in[12];
    const float* bo  = (const float*)d_in[13];
    const float* bp  = (const float*)d_in[14];
    float* out = (float*)d_out;

    cudaFuncSetAttribute(k_step_hmma, cudaFuncAttributeMaxDynamicSharedMemorySize, STEP_SMEM);

    k_init<<<512, 256>>>();
    k_prep<<<128 * 16, 128>>>(Wgh, Wih, Wfh, Woh);
    k_input_proj<<<dim3(32, Tt), 256>>>(x, Wgx, Wix, Wfx, Wox, bg, bi, bf, bo);
    for (int s = 0; s < Tt; s++)
        k_step_hmma<<<128, 256, STEP_SMEM>>>(s);
    k_final<<<Bsz, 256>>>(Wph, bp, out);
}

// round 14
// speedup vs baseline: 3.8964x; 1.0082x over previous
#include <cuda_runtime.h>
#include <cuda_bf16.h>
#include <cstdint>
#include <cstddef>

#define Bsz 128
#define Tt  256
#define Dd  256
#define Hh  1024
#define Cc  1000
#define NCH 16

__device__ float g_xproj[(size_t)Tt * 32 * 128 * 128];   // [t][j][n128][b]
__device__ char  g_wt[(size_t)128 * 2 * NCH * 4096];     // W tiles [J][term][q][n32][k64]
__device__ char  g_ht[(size_t)2 * 2 * NCH * 16384];      // h tiles [ping][term][q][b128][k64]
__device__ float g_c[(size_t)Hh * Bsz];                  // c [hcol][b]
__device__ float g_hp[(size_t)Hh * Bsz];                 // fp32 h for k_final
__device__ unsigned g_bar;                               // grid barrier counter

__device__ __forceinline__ unsigned long long pack2(float lo, float hi) {
    unsigned long long r; asm("mov.b64 %0, {%1, %2};" : "=l"(r) : "f"(lo), "f"(hi)); return r;
}
__device__ __forceinline__ void fma2(unsigned long long &a, unsigned long long x, unsigned long long y) {
    asm("fma.rn.f32x2 %0, %1, %2, %0;" : "+l"(a) : "l"(x), "l"(y));
}
__device__ __forceinline__ float sigm(float x) { return __fdividef(1.f, 1.f + __expf(-x)); }
__device__ __forceinline__ float tanhx(float x) { return 1.f - __fdividef(2.f, __expf(2.f * x) + 1.f); }
__device__ __forceinline__ void cpa16(uint32_t d, const void* s) {
    asm volatile("cp.async.cg.shared.global [%0], [%1], 16;" :: "r"(d), "l"(s));
}
#define CPA_COMMIT() asm volatile("cp.async.commit_group;")
#define CPA_WAIT0()  asm volatile("cp.async.wait_group 0;")
#define SWZ(off) ((off) ^ (((off) >> 3) & 0x70))

__device__ __forceinline__ uint32_t smem_u32(const void* p) {
    uint32_t a; asm("{ .reg .u64 t; cvta.to.shared.u64 t, %1; cvt.u32.u64 %0, t; }" : "=r"(a) : "l"(p)); return a;
}
__device__ __forceinline__ void ldsm4(uint32_t* r, uint32_t a) {
    asm volatile("ldmatrix.sync.aligned.m8n8.x4.shared.b16 {%0,%1,%2,%3}, [%4];"
        : "=r"(r[0]), "=r"(r[1]), "=r"(r[2]), "=r"(r[3]) : "r"(a));
}
__device__ __forceinline__ void ldsm2(uint32_t* r, uint32_t a) {
    asm volatile("ldmatrix.sync.aligned.m8n8.x2.shared.b16 {%0,%1}, [%2];"
        : "=r"(r[0]), "=r"(r[1]) : "r"(a));
}
__device__ __forceinline__ void mma16816(float* d, const uint32_t* a, const uint32_t* b) {
    asm volatile("mma.sync.aligned.m16n8k16.row.col.f32.bf16.bf16.f32 "
        "{%0,%1,%2,%3}, {%4,%5,%6,%7}, {%8,%9}, {%0,%1,%2,%3};"
        : "+f"(d[0]), "+f"(d[1]), "+f"(d[2]), "+f"(d[3])
        : "r"(a[0]), "r"(a[1]), "r"(a[2]), "r"(a[3]), "r"(b[0]), "r"(b[1]));
}

__global__ void k_init() {
    int i = blockIdx.x * blockDim.x + threadIdx.x;
    if (i == 0) g_bar = 0u;
    if (i < 131072) { ((uint32_t*)g_ht)[i] = 0u; g_c[i] = 0.f; }  // ping0 tiles + c
}

// W tiles: [J][term][q][n'32][k64] bf16 swizzled; n' = hcl*4+gate, col = J*8+hcl
__global__ __launch_bounds__(128) void k_prep(
    const float* __restrict__ Wg, const float* __restrict__ Wi,
    const float* __restrict__ Wf, const float* __restrict__ Wo)
{
    int J = blockIdx.x >> 4, q = blockIdx.x & 15;
    char* b0 = g_wt + (size_t)((J * 2 + 0) * NCH + q) * 4096;
    char* b1 = g_wt + (size_t)((J * 2 + 1) * NCH + q) * 4096;
    for (int g = threadIdx.x; g < 256; g += 128) {
        int np = g >> 3, k8 = g & 7;
        int gate = np & 3, hcol = J * 8 + (np >> 2);
        const float* W = (gate < 2) ? (gate == 0 ? Wg : Wi) : (gate == 2 ? Wf : Wo);
        alignas(16) __nv_bfloat16 h8[8], l8[8];
#pragma unroll
        for (int i = 0; i < 8; i++) {
            float w = W[(size_t)(q * 64 + k8 * 8 + i) * Hh + hcol];
            __nv_bfloat16 h = __float2bfloat16(w);
            h8[i] = h; l8[i] = __float2bfloat16(w - __bfloat162float(h));
        }
        uint32_t off = SWZ((uint32_t)(np * 128 + k8 * 16));
        *(uint4*)(b0 + off) = *(uint4*)h8;
        *(uint4*)(b1 + off) = *(uint4*)l8;
    }
}

// phase 1: proven FFMA GEMM, xproj [t][j][n128=gate*32+hcl32][b]
__global__ __launch_bounds__(256, 2) void k_input_proj(
    const float* __restrict__ x,
    const float* __restrict__ Wg, const float* __restrict__ Wi,
    const float* __restrict__ Wf, const float* __restrict__ Wo,
    const float* __restrict__ bg, const float* __restrict__ bi,
    const float* __restrict__ bf, const float* __restrict__ bo)
{
    __shared__ float Ws[32][128];
    __shared__ float Xs[32][132];
    int j = blockIdx.x, t = blockIdx.y;
    int tid = threadIdx.x;
    int tn = tid & 15, tb = tid >> 4;
    int n0 = tn * 8, b0 = tb * 8;
    int jb = j * 32;
    int c4w = tid & 31, gatew = c4w >> 3;
    const float* Wsel = (gatew < 2) ? (gatew == 0 ? Wg : Wi) : (gatew == 2 ? Wf : Wo);
    const float* wsrc0 = Wsel + jb + (c4w & 7) * 4;
    unsigned long long acc[32];
#pragma unroll
    for (int q = 0; q < 32; q++) acc[q] = 0ull;
    for (int kc = 0; kc < Dd / 32; kc++) {
        int k0 = kc * 32;
#pragma unroll
        for (int p = 0; p < 4; p++) {
            int row = p * 8 + (tid >> 5);
            *(float4*)&Ws[row][c4w * 4] = *(const float4*)(wsrc0 + (size_t)(k0 + row) * Hh);
        }
#pragma unroll
        for (int p = 0; p < 4; p++) {
            int fi = p * 256 + tid, b = fi >> 3, d4 = fi & 7;
            float4 v = *(const float4*)&x[((size_t)b * Tt + t) * Dd + k0 + d4 * 4];
            Xs[d4 * 4 + 0][b] = v.x; Xs[d4 * 4 + 1][b] = v.y;
            Xs[d4 * 4 + 2][b] = v.z; Xs[d4 * 4 + 3][b] = v.w;
        }
        __syncthreads();
#pragma unroll 4
        for (int kr = 0; kr < 32; kr++) {
            float4 wA = *(const float4*)&Ws[kr][n0];
            float4 wB = *(const float4*)&Ws[kr][n0 + 4];
            float4 xA = *(const float4*)&Xs[kr][b0];
            float4 xB = *(const float4*)&Xs[kr][b0 + 4];
            unsigned long long w0 = pack2(wA.x, wA.y), w1 = pack2(wA.z, wA.w);
            unsigned long long w2 = pack2(wB.x, wB.y), w3 = pack2(wB.z, wB.w);
            float xv[8] = {xA.x, xA.y, xA.z, xA.w, xB.x, xB.y, xB.z, xB.w};
#pragma unroll
            for (int b = 0; b < 8; b++) {
                unsigned long long xb = pack2(xv[b], xv[b]);
                fma2(acc[0 * 8 + b], w0, xb); fma2(acc[1 * 8 + b], w1, xb);
                fma2(acc[2 * 8 + b], w2, xb); fma2(acc[3 * 8 + b], w3, xb);
            }
        }
        __syncthreads();
    }
    float* outp = g_xproj + (((size_t)t * 32 + j) * 128) * 128;
    int gate = n0 >> 5;
    const float* bsel = (gate < 2) ? (gate == 0 ? bg : bi) : (gate == 2 ? bf : bo);
#pragma unroll
    for (int np = 0; np < 4; np++) {
        int n = n0 + 2 * np;
        float bia0 = bsel[jb + (n & 31)], bia1 = bsel[jb + ((n + 1) & 31)];
#pragma unroll
        for (int b = 0; b < 8; b++) {
            float2 v = *(float2*)&acc[np * 8 + b];
            outp[(size_t)n * 128 + b0 + b]       = v.x + bia0;
            outp[(size_t)(n + 1) * 128 + b0 + b] = v.y + bia1;
        }
    }
}

// phase 2: PERSISTENT HMMA stepper. grid 128 (J), 256 thr (8 warps).
// smem: W resident [term][q] 128KB @0 | A 2 bufs x 32KB {Ahi 16K|Alo 16K} @131072
// epilogue overlay at 131072: Ps[128][33] fp32 (16.9K), Hhi @+17408, Hlo @+19456
#define W_SMEM   131072
#define A_BUF    32768
#define STEP_SMEM (W_SMEM + 2 * A_BUF)
__global__ __launch_bounds__(256, 1) void k_persist()
{
    extern __shared__ __align__(1024) char smx[];
    uint32_t sb = smem_u32(smx);
    int tid = threadIdx.x, wid = tid >> 5, lane = tid & 31;
    int wm = wid & 3, wn = wid >> 2;
    int J = blockIdx.x;

    // load full W slice (128 KB) once
    {
        const char* src = g_wt + (size_t)J * W_SMEM;
#pragma unroll
        for (int p = 0; p < 32; p++) {
            int g = p * 256 + tid;
            cpa16(sb + g * 16, src + g * 16);
        }
        CPA_COMMIT(); CPA_WAIT0();
        __syncthreads();
    }

    int selA = lane >> 3;
    int rowA = (lane & 7) + (selA & 1) * 8;
    int kcA = (selA >> 1) * 8;
    int rowB = lane & 7;
    int kcB = ((lane >> 3) & 1) * 8;
    uint32_t sbA = sb + W_SMEM;

    for (int s = 0; s < Tt; s++) {
        int pin = s & 1, pout = pin ^ 1;
        const char* gAh = g_ht + (size_t)(pin * 2 + 0) * NCH * 16384;
        const char* gAl = g_ht + (size_t)(pin * 2 + 1) * NCH * 16384;

        float d[16];
#pragma unroll
        for (int q = 0; q < 16; q++) d[q] = 0.f;

        // prefetch chunk 0 -> buf 0
#pragma unroll
        for (int p = 0; p < 4; p++) {
            int g = p * 256 + tid;
            cpa16(sbA + g * 16, gAh + g * 16);
            cpa16(sbA + 16384 + g * 16, gAl + g * 16);
        }
        CPA_COMMIT();

        for (int q = 0; q < NCH; q++) {
            CPA_WAIT0();
            __syncthreads();
            if (q < 15) {
                uint32_t bn = sbA + ((q + 1) & 1) * A_BUF;
                const char* ah = gAh + (size_t)(q + 1) * 16384;
                const char* al = gAl + (size_t)(q + 1) * 16384;
#pragma unroll
                for (int p = 0; p < 4; p++) {
                    int g = p * 256 + tid;
                    cpa16(bn + g * 16, ah + g * 16);
                    cpa16(bn + 16384 + g * 16, al + g * 16);
                }
                CPA_COMMIT();
            }
            uint32_t aAh = sbA + (q & 1) * A_BUF;
            uint32_t aAl = aAh + 16384;
            uint32_t aBh = sb + q * 4096;
            uint32_t aBl = sb + 65536 + q * 4096;
#pragma unroll
            for (int ks = 0; ks < 4; ks++) {
                uint32_t Ah[2][4], Al[2][4], Bh[2][2], Bl[2][2];
#pragma unroll
                for (int mb = 0; mb < 2; mb++) {
                    uint32_t offA = SWZ((uint32_t)((wm * 32 + mb * 16 + rowA) * 128 + (ks * 16 + kcA) * 2));
                    ldsm4(Ah[mb], aAh + offA);
                    ldsm4(Al[mb], aAl + offA);
                }
#pragma unroll
                for (int nb = 0; nb < 2; nb++) {
                    uint32_t offB = SWZ((uint32_t)((wn * 16 + nb * 8 + rowB) * 128 + (ks * 16 + kcB) * 2));
                    ldsm2(Bh[nb], aBh + offB);
                    ldsm2(Bl[nb], aBl + offB);
                }
#pragma unroll
                for (int mb = 0; mb < 2; mb++)
#pragma unroll
                    for (int nb = 0; nb < 2; nb++) {
                        float* dd = d + (mb * 2 + nb) * 4;
                        mma16816(dd, Ah[mb], Bh[nb]);
                        mma16816(dd, Ah[mb], Bl[nb]);
                        mma16816(dd, Al[mb], Bh[nb]);
                    }
            }
            __syncthreads();
        }

        // epilogue (overlay on A-buf region; A bufs idle until next step's prefetch)
        float* Ps = (float*)(smx + W_SMEM);
        __nv_bfloat16* Hhi = (__nv_bfloat16*)(smx + W_SMEM + 17408);
        __nv_bfloat16* Hlo = (__nv_bfloat16*)(smx + W_SMEM + 19456);
        int r = lane >> 2, c = (lane & 3) * 2;
#pragma unroll
        for (int mb = 0; mb < 2; mb++)
#pragma unroll
            for (int nb = 0; nb < 2; nb++) {
                float* dd = d + (mb * 2 + nb) * 4;
                int m = wm * 32 + mb * 16 + r, n = wn * 16 + nb * 8 + c;
                Ps[m * 33 + n] = dd[0];       Ps[m * 33 + n + 1] = dd[1];
                Ps[(m + 8) * 33 + n] = dd[2]; Ps[(m + 8) * 33 + n + 1] = dd[3];
            }
        __syncthreads();

        int b = tid & 127, hh4 = (tid >> 7) * 4;
#pragma unroll
        for (int e = 0; e < 4; e++) {
            int hcl = hh4 + e;
            int hcg = J * 8 + hcl;
            int j = hcg >> 5, r32 = hcg & 31;
            const float* xp = g_xproj + (((size_t)s * 32 + j) * 128 + r32) * 128 + b;
            float pg = Ps[b * 33 + hcl * 4 + 0] + xp[0];
            float pi = Ps[b * 33 + hcl * 4 + 1] + xp[32 * 128];
            float pf = Ps[b * 33 + hcl * 4 + 2] + xp[64 * 128];
            float po = Ps[b * 33 + hcl * 4 + 3] + xp[96 * 128];
            size_t ci = (size_t)hcg * Bsz + b;
            float gg = tanhx(pg), ii = sigm(pi), ff = sigm(pf), oo = sigm(po);
            float cn = gg * ii + g_c[ci] * ff;
            g_c[ci] = cn;
            float hv = tanhx(cn) * oo;
            g_hp[ci] = hv;
            __nv_bfloat16 hb = __float2bfloat16(hv);
            Hhi[b * 8 + hcl] = hb;
            Hlo[b * 8 + hcl] = __float2bfloat16(hv - __bfloat162float(hb));
        }
        __syncthreads();

        {
            int bb = tid & 127, term = tid >> 7;
            int q = J >> 3;
            uint32_t off = SWZ((uint32_t)(bb * 128 + (J & 7) * 16));
            char* dst = g_ht + (size_t)((pout * 2 + term) * NCH + q) * 16384 + off;
            const __nv_bfloat16* src = term ? Hlo : Hhi;
            *(uint4*)dst = *(const uint4*)&src[bb * 8];
        }

        // grid barrier: release h writes, wait for all 128 CTAs
        __syncthreads();
        __threadfence();
        if (tid == 0) {
            atomicAdd(&g_bar, 1u);
            unsigned target = (unsigned)(s + 1) * 128u;
            unsigned v;
            do {
                asm volatile("ld.acquire.gpu.global.u32 %0, [%1];" : "=r"(v) : "l"(&g_bar));
                if (v < target) __nanosleep(64);
            } while (v < target);
        }
        __syncthreads();
    }
}

// phase 3
__global__ __launch_bounds__(256) void k_final(const float* __restrict__ Wph,
                                               const float* __restrict__ bp,
                                               float* __restrict__ out)
{
    __shared__ float hs[Hh];
    __shared__ float ls[Cc];
    __shared__ float red[256];
    int b = blockIdx.x, tid = threadIdx.x;
    for (int k = tid; k < Hh; k += 256) hs[k] = g_hp[(size_t)k * Bsz + b];
    __syncthreads();
    float acc[4] = {0.f, 0.f, 0.f, 0.f};
    for (int k = 0; k < Hh; k++) {
        float hk = hs[k];
        const float* wr = Wph + (size_t)k * Cc;
#pragma unroll
        for (int q = 0; q < 4; q++) { int n = tid + q * 256; if (n < Cc) acc[q] = fmaf(hk, wr[n], acc[q]); }
    }
    float lmax = -1e30f;
#pragma unroll
    for (int q = 0; q < 4; q++) { int n = tid + q * 256; if (n < Cc) { float v = acc[q] + bp[n]; ls[n] = v; lmax = fmaxf(lmax, v); } }
    red[tid] = lmax; __syncthreads();
    for (int st = 128; st > 0; st >>= 1) { if (tid < st) red[tid] = fmaxf(red[tid], red[tid + st]); __syncthreads(); }
    float mx = red[0]; __syncthreads();
    float lsum = 0.f;
#pragma unroll
    for (int q = 0; q < 4; q++) { int n = tid + q * 256; if (n < Cc) lsum += expf(ls[n] - mx); }
    red[tid] = lsum; __syncthreads();
    for (int st = 128; st > 0; st >>= 1) { if (tid < st) red[tid] += red[tid + st]; __syncthreads(); }
    float lse = logf(red[0]);
#pragma unroll
    for (int q = 0; q < 4; q++) { int n = tid + q * 256; if (n < Cc) out[(size_t)b * Cc + n] = ls[n] - mx - lse; }
}

extern "C" void kernel_launch(void* const* d_in, const int* in_sizes, int n_in,
                              void* d_out, int out_size) {
    const float* x   = (const float*)d_in[0];
    const float* Wgx = (const float*)d_in[1];
    const float* Wix = (const float*)d_in[2];
    const float* Wfx = (const float*)d_in[3];
    const float* Wox = (const float*)d_in[4];
    const float* Wgh = (const float*)d_in[5];
    const float* Wih = (const float*)d_in[6];
    const float* Wfh = (const float*)d_in[7];
    const float* Woh = (const float*)d_in[8];
    const float* Wph = (const float*)d_in[9];
    const float* bg  = (const float*)d_in[10];
    const float* bi  = (const float*)d_in[11];
    const float* bf  = (const float*)d_in[12];
    const float* bo  = (const float*)d_in[13];
    const float* bp  = (const float*)d_in[14];
    float* out = (float*)d_out;

    cudaFuncSetAttribute(k_persist, cudaFuncAttributeMaxDynamicSharedMemorySize, STEP_SMEM);

    k_init<<<512, 256>>>();
    k_prep<<<128 * 16, 128>>>(Wgh, Wih, Wfh, Woh);
    k_input_proj<<<dim3(32, Tt), 256>>>(x, Wgx, Wix, Wfx, Wox, bg, bi, bf, bo);
    k_persist<<<128, 256, STEP_SMEM>>>();
    k_final<<<Bsz, 256>>>(Wph, bp, out);
}

// round 16
// speedup vs baseline: 4.2337x; 1.0866x over previous
#include <cuda_runtime.h>
#include <cuda_bf16.h>
#include <cstdint>
#include <cstddef>

#define Bsz 128
#define Tt  256
#define Dd  256
#define Hh  1024
#define Cc  1000
#define NCH 16

__device__ float g_xproj[(size_t)Tt * 32 * 128 * 128];   // [t][j][n128][b]
__device__ char  g_wt[(size_t)128 * 2 * NCH * 4096];     // W tiles [J][term][q][n32][k64]
__device__ char  g_ht[(size_t)2 * 2 * NCH * 16384];      // h tiles [ping][term][q][b128][k64]
__device__ float g_c[(size_t)Hh * Bsz];                  // c [hcol][b]
__device__ float g_hp[(size_t)Hh * Bsz];                 // fp32 h for k_final
__device__ unsigned g_bar;                               // grid barrier counter

__device__ __forceinline__ unsigned long long pack2(float lo, float hi) {
    unsigned long long r; asm("mov.b64 %0, {%1, %2};" : "=l"(r) : "f"(lo), "f"(hi)); return r;
}
__device__ __forceinline__ void fma2(unsigned long long &a, unsigned long long x, unsigned long long y) {
    asm("fma.rn.f32x2 %0, %1, %2, %0;" : "+l"(a) : "l"(x), "l"(y));
}
__device__ __forceinline__ float sigm(float x) { return __fdividef(1.f, 1.f + __expf(-x)); }
__device__ __forceinline__ float tanhx(float x) { return 1.f - __fdividef(2.f, __expf(2.f * x) + 1.f); }
__device__ __forceinline__ void cpa16(uint32_t d, const void* s) {
    asm volatile("cp.async.cg.shared.global [%0], [%1], 16;" :: "r"(d), "l"(s));
}
#define CPA_COMMIT() asm volatile("cp.async.commit_group;")
#define CPA_WAIT0()  asm volatile("cp.async.wait_group 0;")
#define CPA_WAIT1()  asm volatile("cp.async.wait_group 1;")
#define SWZ(off) ((off) ^ (((off) >> 3) & 0x70))

__device__ __forceinline__ uint32_t smem_u32(const void* p) {
    uint32_t a; asm("{ .reg .u64 t; cvta.to.shared.u64 t, %1; cvt.u32.u64 %0, t; }" : "=r"(a) : "l"(p)); return a;
}
__device__ __forceinline__ void ldsm4(uint32_t* r, uint32_t a) {
    asm volatile("ldmatrix.sync.aligned.m8n8.x4.shared.b16 {%0,%1,%2,%3}, [%4];"
        : "=r"(r[0]), "=r"(r[1]), "=r"(r[2]), "=r"(r[3]) : "r"(a));
}
__device__ __forceinline__ void ldsm2(uint32_t* r, uint32_t a) {
    asm volatile("ldmatrix.sync.aligned.m8n8.x2.shared.b16 {%0,%1}, [%2];"
        : "=r"(r[0]), "=r"(r[1]) : "r"(a));
}
__device__ __forceinline__ void mma16816(float* d, const uint32_t* a, const uint32_t* b) {
    asm volatile("mma.sync.aligned.m16n8k16.row.col.f32.bf16.bf16.f32 "
        "{%0,%1,%2,%3}, {%4,%5,%6,%7}, {%8,%9}, {%0,%1,%2,%3};"
        : "+f"(d[0]), "+f"(d[1]), "+f"(d[2]), "+f"(d[3])
        : "r"(a[0]), "r"(a[1]), "r"(a[2]), "r"(a[3]), "r"(b[0]), "r"(b[1]));
}

__global__ void k_init() {
    int i = blockIdx.x * blockDim.x + threadIdx.x;
    if (i == 0) g_bar = 0u;
    if (i < 131072) { ((uint32_t*)g_ht)[i] = 0u; g_c[i] = 0.f; }  // ping0 tiles + c
}

// W tiles: [J][term][q][n'32][k64] bf16 swizzled; n' = hcl*4+gate, col = J*8+hcl
__global__ __launch_bounds__(128) void k_prep(
    const float* __restrict__ Wg, const float* __restrict__ Wi,
    const float* __restrict__ Wf, const float* __restrict__ Wo)
{
    int J = blockIdx.x >> 4, q = blockIdx.x & 15;
    char* b0 = g_wt + (size_t)((J * 2 + 0) * NCH + q) * 4096;
    char* b1 = g_wt + (size_t)((J * 2 + 1) * NCH + q) * 4096;
    for (int g = threadIdx.x; g < 256; g += 128) {
        int np = g >> 3, k8 = g & 7;
        int gate = np & 3, hcol = J * 8 + (np >> 2);
        const float* W = (gate < 2) ? (gate == 0 ? Wg : Wi) : (gate == 2 ? Wf : Wo);
        alignas(16) __nv_bfloat16 h8[8], l8[8];
#pragma unroll
        for (int i = 0; i < 8; i++) {
            float w = W[(size_t)(q * 64 + k8 * 8 + i) * Hh + hcol];
            __nv_bfloat16 h = __float2bfloat16(w);
            h8[i] = h; l8[i] = __float2bfloat16(w - __bfloat162float(h));
        }
        uint32_t off = SWZ((uint32_t)(np * 128 + k8 * 16));
        *(uint4*)(b0 + off) = *(uint4*)h8;
        *(uint4*)(b1 + off) = *(uint4*)l8;
    }
}

// phase 1: proven FFMA GEMM, xproj [t][j][n128=gate*32+hcl32][b]
__global__ __launch_bounds__(256, 2) void k_input_proj(
    const float* __restrict__ x,
    const float* __restrict__ Wg, const float* __restrict__ Wi,
    const float* __restrict__ Wf, const float* __restrict__ Wo,
    const float* __restrict__ bg, const float* __restrict__ bi,
    const float* __restrict__ bf, const float* __restrict__ bo)
{
    __shared__ float Ws[32][128];
    __shared__ float Xs[32][132];
    int j = blockIdx.x, t = blockIdx.y;
    int tid = threadIdx.x;
    int tn = tid & 15, tb = tid >> 4;
    int n0 = tn * 8, b0 = tb * 8;
    int jb = j * 32;
    int c4w = tid & 31, gatew = c4w >> 3;
    const float* Wsel = (gatew < 2) ? (gatew == 0 ? Wg : Wi) : (gatew == 2 ? Wf : Wo);
    const float* wsrc0 = Wsel + jb + (c4w & 7) * 4;
    unsigned long long acc[32];
#pragma unroll
    for (int q = 0; q < 32; q++) acc[q] = 0ull;
    for (int kc = 0; kc < Dd / 32; kc++) {
        int k0 = kc * 32;
#pragma unroll
        for (int p = 0; p < 4; p++) {
            int row = p * 8 + (tid >> 5);
            *(float4*)&Ws[row][c4w * 4] = *(const float4*)(wsrc0 + (size_t)(k0 + row) * Hh);
        }
#pragma unroll
        for (int p = 0; p < 4; p++) {
            int fi = p * 256 + tid, b = fi >> 3, d4 = fi & 7;
            float4 v = *(const float4*)&x[((size_t)b * Tt + t) * Dd + k0 + d4 * 4];
            Xs[d4 * 4 + 0][b] = v.x; Xs[d4 * 4 + 1][b] = v.y;
            Xs[d4 * 4 + 2][b] = v.z; Xs[d4 * 4 + 3][b] = v.w;
        }
        __syncthreads();
#pragma unroll 4
        for (int kr = 0; kr < 32; kr++) {
            float4 wA = *(const float4*)&Ws[kr][n0];
            float4 wB = *(const float4*)&Ws[kr][n0 + 4];
            float4 xA = *(const float4*)&Xs[kr][b0];
            float4 xB = *(const float4*)&Xs[kr][b0 + 4];
            unsigned long long w0 = pack2(wA.x, wA.y), w1 = pack2(wA.z, wA.w);
            unsigned long long w2 = pack2(wB.x, wB.y), w3 = pack2(wB.z, wB.w);
            float xv[8] = {xA.x, xA.y, xA.z, xA.w, xB.x, xB.y, xB.z, xB.w};
#pragma unroll
            for (int b = 0; b < 8; b++) {
                unsigned long long xb = pack2(xv[b], xv[b]);
                fma2(acc[0 * 8 + b], w0, xb); fma2(acc[1 * 8 + b], w1, xb);
                fma2(acc[2 * 8 + b], w2, xb); fma2(acc[3 * 8 + b], w3, xb);
            }
        }
        __syncthreads();
    }
    float* outp = g_xproj + (((size_t)t * 32 + j) * 128) * 128;
    int gate = n0 >> 5;
    const float* bsel = (gate < 2) ? (gate == 0 ? bg : bi) : (gate == 2 ? bf : bo);
#pragma unroll
    for (int np = 0; np < 4; np++) {
        int n = n0 + 2 * np;
        float bia0 = bsel[jb + (n & 31)], bia1 = bsel[jb + ((n + 1) & 31)];
#pragma unroll
        for (int b = 0; b < 8; b++) {
            float2 v = *(float2*)&acc[np * 8 + b];
            outp[(size_t)n * 128 + b0 + b]       = v.x + bia0;
            outp[(size_t)(n + 1) * 128 + b0 + b] = v.y + bia1;
        }
    }
}

// phase 2: PERSISTENT HMMA stepper, 3-buffer A pipeline. grid 128 (J), 256 thr.
// smem: W resident 128KB @0 | A 3 bufs x 32KB {Ahi 16K|Alo 16K} @131072 = 224KB
// epilogue overlay at W_SMEM: Ps[128][33] fp32, Hhi @+17408, Hlo @+19456
#define W_SMEM   131072
#define A_BUF    32768
#define STEP_SMEM (W_SMEM + 3 * A_BUF)
__global__ __launch_bounds__(256, 1) void k_persist()
{
    extern __shared__ __align__(1024) char smx[];
    uint32_t sb = smem_u32(smx);
    int tid = threadIdx.x, wid = tid >> 5, lane = tid & 31;
    int wm = wid & 3, wn = wid >> 2;
    int J = blockIdx.x;

    // load full W slice (128 KB) once
    {
        const char* src = g_wt + (size_t)J * W_SMEM;
#pragma unroll
        for (int p = 0; p < 32; p++) {
            int g = p * 256 + tid;
            cpa16(sb + g * 16, src + g * 16);
        }
        CPA_COMMIT(); CPA_WAIT0();
        __syncthreads();
    }

    int selA = lane >> 3;
    int rowA = (lane & 7) + (selA & 1) * 8;
    int kcA = (selA >> 1) * 8;
    int rowB = lane & 7;
    int kcB = ((lane >> 3) & 1) * 8;
    uint32_t sbA = sb + W_SMEM;
    int bq = tid & 127, hh4 = (tid >> 7) * 4;

    for (int s = 0; s < Tt; s++) {
        int pin = s & 1, pout = pin ^ 1;
        const char* gAh = g_ht + (size_t)(pin * 2 + 0) * NCH * 16384;
        const char* gAl = g_ht + (size_t)(pin * 2 + 1) * NCH * 16384;

        // prefetch epilogue xproj operands into registers (DRAM latency absorbed by loop)
        float xpre[16];
#pragma unroll
        for (int e = 0; e < 4; e++) {
            int hcg = J * 8 + hh4 + e;
            const float* xp = g_xproj + (((size_t)s * 32 + (hcg >> 5)) * 128 + (hcg & 31)) * 128 + bq;
            xpre[e * 4 + 0] = xp[0];
            xpre[e * 4 + 1] = xp[32 * 128];
            xpre[e * 4 + 2] = xp[64 * 128];
            xpre[e * 4 + 3] = xp[96 * 128];
        }

        float d[16];
#pragma unroll
        for (int q = 0; q < 16; q++) d[q] = 0.f;

        // prefetch chunks 0,1 -> bufs 0,1
#pragma unroll
        for (int q0 = 0; q0 < 2; q0++) {
            uint32_t bs = sbA + q0 * A_BUF;
#pragma unroll
            for (int p = 0; p < 4; p++) {
                int g = p * 256 + tid;
                cpa16(bs + g * 16, gAh + (size_t)q0 * 16384 + g * 16);
                cpa16(bs + 16384 + g * 16, gAl + (size_t)q0 * 16384 + g * 16);
            }
            CPA_COMMIT();
        }

        for (int q = 0; q < NCH; q++) {
            if (q < 14) { CPA_WAIT1(); } else { CPA_WAIT0(); }
            __syncthreads();
            if (q + 2 < NCH) {    // issue load(q+2) -> buf (q+2)%3 (freed by compute(q-1))
                int qn = q + 2;
                uint32_t bn = sbA + (qn % 3) * A_BUF;
#pragma unroll
                for (int p = 0; p < 4; p++) {
                    int g = p * 256 + tid;
                    cpa16(bn + g * 16, gAh + (size_t)qn * 16384 + g * 16);
                    cpa16(bn + 16384 + g * 16, gAl + (size_t)qn * 16384 + g * 16);
                }
                CPA_COMMIT();
            }
            uint32_t aAh = sbA + (q % 3) * A_BUF;
            uint32_t aAl = aAh + 16384;
            uint32_t aBh = sb + q * 4096;
            uint32_t aBl = sb + 65536 + q * 4096;
#pragma unroll
            for (int ks = 0; ks < 4; ks++) {
                uint32_t Ah[2][4], Al[2][4], Bh[2][2], Bl[2][2];
#pragma unroll
                for (int mb = 0; mb < 2; mb++) {
                    uint32_t offA = SWZ((uint32_t)((wm * 32 + mb * 16 + rowA) * 128 + (ks * 16 + kcA) * 2));
                    ldsm4(Ah[mb], aAh + offA);
                    ldsm4(Al[mb], aAl + offA);
                }
#pragma unroll
                for (int nb = 0; nb < 2; nb++) {
                    uint32_t offB = SWZ((uint32_t)((wn * 16 + nb * 8 + rowB) * 128 + (ks * 16 + kcB) * 2));
                    ldsm2(Bh[nb], aBh + offB);
                    ldsm2(Bl[nb], aBl + offB);
                }
#pragma unroll
                for (int mb = 0; mb < 2; mb++)
#pragma unroll
                    for (int nb = 0; nb < 2; nb++) {
                        float* dd = d + (mb * 2 + nb) * 4;
                        mma16816(dd, Ah[mb], Bh[nb]);
                        mma16816(dd, Ah[mb], Bl[nb]);
                        mma16816(dd, Al[mb], Bh[nb]);
                    }
            }
        }
        __syncthreads();   // all reads of buf0 (chunk 15) done before Ps overlay

        // epilogue (overlay on A buf0)
        float* Ps = (float*)(smx + W_SMEM);
        __nv_bfloat16* Hhi = (__nv_bfloat16*)(smx + W_SMEM + 17408);
        __nv_bfloat16* Hlo = (__nv_bfloat16*)(smx + W_SMEM + 19456);
        int r = lane >> 2, c = (lane & 3) * 2;
#pragma unroll
        for (int mb = 0; mb < 2; mb++)
#pragma unroll
            for (int nb = 0; nb < 2; nb++) {
                float* dd = d + (mb * 2 + nb) * 4;
                int m = wm * 32 + mb * 16 + r, n = wn * 16 + nb * 8 + c;
                Ps[m * 33 + n] = dd[0];       Ps[m * 33 + n + 1] = dd[1];
                Ps[(m + 8) * 33 + n] = dd[2]; Ps[(m + 8) * 33 + n + 1] = dd[3];
            }
        __syncthreads();

#pragma unroll
        for (int e = 0; e < 4; e++) {
            int hcl = hh4 + e;
            int hcg = J * 8 + hcl;
            float pg = Ps[bq * 33 + hcl * 4 + 0] + xpre[e * 4 + 0];
            float pi = Ps[bq * 33 + hcl * 4 + 1] + xpre[e * 4 + 1];
            float pf = Ps[bq * 33 + hcl * 4 + 2] + xpre[e * 4 + 2];
            float po = Ps[bq * 33 + hcl * 4 + 3] + xpre[e * 4 + 3];
            size_t ci = (size_t)hcg * Bsz + bq;
            float gg = tanhx(pg), ii = sigm(pi), ff = sigm(pf), oo = sigm(po);
            float cn = gg * ii + g_c[ci] * ff;
            g_c[ci] = cn;
            float hv = tanhx(cn) * oo;
            g_hp[ci] = hv;
            __nv_bfloat16 hb = __float2bfloat16(hv);
            Hhi[bq * 8 + hcl] = hb;
            Hlo[bq * 8 + hcl] = __float2bfloat16(hv - __bfloat162float(hb));
        }
        __syncthreads();

        {
            int bb = tid & 127, term = tid >> 7;
            int q = J >> 3;
            uint32_t off = SWZ((uint32_t)(bb * 128 + (J & 7) * 16));
            char* dst = g_ht + (size_t)((pout * 2 + term) * NCH + q) * 16384 + off;
            const __nv_bfloat16* src = term ? Hlo : Hhi;
            *(uint4*)dst = *(const uint4*)&src[bb * 8];
        }

        // grid barrier: release h writes, wait for all 128 CTAs
        __syncthreads();
        __threadfence();
        if (tid == 0) {
            atomicAdd(&g_bar, 1u);
            unsigned target = (unsigned)(s + 1) * 128u;
            unsigned v;
            do {
                asm volatile("ld.acquire.gpu.global.u32 %0, [%1];" : "=r"(v) : "l"(&g_bar));
                if (v < target) __nanosleep(32);
            } while (v < target);
        }
        __syncthreads();
    }
}

// phase 3
__global__ __launch_bounds__(256) void k_final(const float* __restrict__ Wph,
                                               const float* __restrict__ bp,
                                               float* __restrict__ out)
{
    __shared__ float hs[Hh];
    __shared__ float ls[Cc];
    __shared__ float red[256];
    int b = blockIdx.x, tid = threadIdx.x;
    for (int k = tid; k < Hh; k += 256) hs[k] = g_hp[(size_t)k * Bsz + b];
    __syncthreads();
    float acc[4] = {0.f, 0.f, 0.f, 0.f};
    for (int k = 0; k < Hh; k++) {
        float hk = hs[k];
        const float* wr = Wph + (size_t)k * Cc;
#pragma unroll
        for (int q = 0; q < 4; q++) { int n = tid + q * 256; if (n < Cc) acc[q] = fmaf(hk, wr[n], acc[q]); }
    }
    float lmax = -1e30f;
#pragma unroll
    for (int q = 0; q < 4; q++) { int n = tid + q * 256; if (n < Cc) { float v = acc[q] + bp[n]; ls[n] = v; lmax = fmaxf(lmax, v); } }
    red[tid] = lmax; __syncthreads();
    for (int st = 128; st > 0; st >>= 1) { if (tid < st) red[tid] = fmaxf(red[tid], red[tid + st]); __syncthreads(); }
    float mx = red[0]; __syncthreads();
    float lsum = 0.f;
#pragma unroll
    for (int q = 0; q < 4; q++) { int n = tid + q * 256; if (n < Cc) lsum += expf(ls[n] - mx); }
    red[tid] = lsum; __syncthreads();
    for (int st = 128; st > 0; st >>= 1) { if (tid < st) red[tid] += red[tid + st]; __syncthreads(); }
    float lse = logf(red[0]);
#pragma unroll
    for (int q = 0; q < 4; q++) { int n = tid + q * 256; if (n < Cc) out[(size_t)b * Cc + n] = ls[n] - mx - lse; }
}

extern "C" void kernel_launch(void* const* d_in, const int* in_sizes, int n_in,
                              void* d_out, int out_size) {
    const float* x   = (const float*)d_in[0];
    const float* Wgx = (const float*)d_in[1];
    const float* Wix = (const float*)d_in[2];
    const float* Wfx = (const float*)d_in[3];
    const float* Wox = (const float*)d_in[4];
    const float* Wgh = (const float*)d_in[5];
    const float* Wih = (const float*)d_in[6];
    const float* Wfh = (const float*)d_in[7];
    const float* Woh = (const float*)d_in[8];
    const float* Wph = (const float*)d_in[9];
    const float* bg  = (const float*)d_in[10];
    const float* bi  = (const float*)d_in[11];
    const float* bf  = (const float*)d_in[12];
    const float* bo  = (const float*)d_in[13];
    const float* bp  = (const float*)d_in[14];
    float* out = (float*)d_out;

    cudaFuncSetAttribute(k_persist, cudaFuncAttributeMaxDynamicSharedMemorySize, STEP_SMEM);

    k_init<<<512, 256>>>();
    k_prep<<<128 * 16, 128>>>(Wgh, Wih, Wfh, Woh);
    k_input_proj<<<dim3(32, Tt), 256>>>(x, Wgx, Wix, Wfx, Wox, bg, bi, bf, bo);
    k_persist<<<128, 256, STEP_SMEM>>>();
    k_final<<<Bsz, 256>>>(Wph, bp, out);
}